// round 15
// baseline (speedup 1.0000x reference)
#include <cuda_runtime.h>
#include <cuda_bf16.h>
#include <math.h>
#include <stdint.h>

// ============================================================================
// PCLinear via mma.sync bf16x3 (hi/lo split, 3-term compensated product).
// R15 = R14 host flow (iteration-0 algebraic elimination) + restructured GEMM
// inner loop: both K-halves (ks=0,1) of a chunk are processed INTERLEAVED,
// giving two independent ldsm->MMA dependency chains so the scheduler can
// cover ldsm latency with the other chain's MMAs. (R14 analysis: tensor pipe
// 58%, ~1250 bubble cyc/chunk from serial ldsm->MMA dependencies at the
// 255-reg cap.)
// ============================================================================

#define GK     2048
#define MAT    (GK * GK)
#define XROWS  8192
#define XMAT   (XROWS * GK)

#define CHUNK    32
#define NCH      (GK / CHUNK)       // 64
#define LDS_B    80                 // smem row stride (40 bf16): conflict-free ldsm
#define TILE_B   (128 * LDS_B)      // 10240 per tile
#define STAGE_B  (4 * TILE_B)       // Ah, Al, Bh, Bl
#define SMEM_NEED (1024 + 2 * STAGE_B)   // ~83KB -> 2 CTAs/SM

// -------------------- device scratch (static, no allocs) --------------------
__device__ __nv_bfloat16 g_wh[MAT],  g_wl[MAT];
__device__ __nv_bfloat16 g_u0h[MAT], g_u0l[MAT];
__device__ __nv_bfloat16 g_u1h[MAT], g_u1l[MAT];
__device__ __nv_bfloat16 g_t0h[MAT], g_t0l[MAT];
__device__ __nv_bfloat16 g_t1h[MAT], g_t1l[MAT];
__device__ __nv_bfloat16 g_gh[MAT],  g_gl[MAT];
__device__ __nv_bfloat16 g_eh[MAT],  g_el[MAT];
__device__ __nv_bfloat16 g_xh[XMAT], g_xl[XMAT];
__device__ double g_accum;
__device__ float  g_scalars[5];
// [0]=w_norm [1]=1/w_norm [2]=w_norm*gamma [3]=1/w_norm^2 [4]=1/w_norm^4

// -------------------- low-level helpers --------------------
__device__ __forceinline__ uint32_t smem_to_u32(const void* p) {
    uint32_t a;
    asm("{ .reg .u64 t; cvta.to.shared.u64 t, %1; cvt.u32.u64 %0, t; }"
        : "=r"(a) : "l"(p));
    return a;
}
__device__ __forceinline__ void ldsm_x4(uint32_t* r, uint32_t addr) {
    asm volatile("ldmatrix.sync.aligned.m8n8.x4.shared.b16 {%0,%1,%2,%3}, [%4];"
                 : "=r"(r[0]), "=r"(r[1]), "=r"(r[2]), "=r"(r[3]) : "r"(addr));
}
__device__ __forceinline__ void mma_bf16(float* c, const uint32_t* a, const uint32_t* b) {
    asm volatile("mma.sync.aligned.m16n8k16.row.col.f32.bf16.bf16.f32 "
                 "{%0,%1,%2,%3}, {%4,%5,%6,%7}, {%8,%9}, {%0,%1,%2,%3};"
                 : "+f"(c[0]), "+f"(c[1]), "+f"(c[2]), "+f"(c[3])
                 : "r"(a[0]), "r"(a[1]), "r"(a[2]), "r"(a[3]),
                   "r"(b[0]), "r"(b[1]));
}
__device__ __forceinline__ void cp16(uint32_t dst, const void* src) {
    asm volatile("cp.async.cg.shared.global [%0], [%1], 16;" :: "r"(dst), "l"(src));
}
#define CP_COMMIT() asm volatile("cp.async.commit_group;" ::: "memory")
#define CP_WAIT1()  asm volatile("cp.async.wait_group 1;" ::: "memory")
#define CP_WAIT0()  asm volatile("cp.async.wait_group 0;" ::: "memory")

// ============================================================================
// bf16x3 GEMM: C[m,n] = alphaEff * sum_k (Ah+Al)[m,k]*(Bh+Bl)[n,k]
//              (+ beta*(Dh+Dl)); writes bf16 hi/lo (oH/oL) and/or fp32 (oF);
//              sumsq!=0 ALSO accumulates ||raw acc||_F^2 into g_accum.
// CTA 128x128, 4 warps (2x2), warp tile 64x64, K-chunk 32, 128 threads.
// Inner loop: ks=0 and ks=1 interleaved (2 independent dependency chains).
// ============================================================================
__global__ __launch_bounds__(128, 2)
void gemm_bf16x3_kernel(const __nv_bfloat16* __restrict__ gAh,
                        const __nv_bfloat16* __restrict__ gAl,
                        const __nv_bfloat16* __restrict__ gBh,
                        const __nv_bfloat16* __restrict__ gBl,
                        __nv_bfloat16* __restrict__ oH,
                        __nv_bfloat16* __restrict__ oL,
                        float* __restrict__ oF,
                        const __nv_bfloat16* __restrict__ dH,
                        const __nv_bfloat16* __restrict__ dL,
                        float alpha, float beta, int alphaIdx, int sumsq)
{
    extern __shared__ char smem_raw[];
    const uint32_t smem_u = (smem_to_u32(smem_raw) + 1023u) & ~1023u;

    const int tid  = threadIdx.x;
    const int wid  = tid >> 5;
    const int lane = tid & 31;
    const int wm   = wid >> 1;        // 0..1 (64-row half)
    const int wn   = wid & 1;         // 0..1 (64-col half)
    const int row0 = blockIdx.y * 128;
    const int col0 = blockIdx.x * 128;

    const uint32_t aCore = (uint32_t)(wm * 64 * LDS_B + (lane & 15) * LDS_B
                                      + (lane >> 4) * 16);
    const uint32_t bCore = (uint32_t)(wn * 64 * LDS_B + (lane & 7) * LDS_B
                                      + ((lane >> 3) & 1) * 16
                                      + ((lane >> 4) & 1) * 8 * LDS_B);

    float acc[4][8][4];
    #pragma unroll
    for (int mt = 0; mt < 4; mt++)
        #pragma unroll
        for (int nt = 0; nt < 8; nt++)
            #pragma unroll
            for (int i = 0; i < 4; i++) acc[mt][nt][i] = 0.0f;

    const __nv_bfloat16* srcs[4] = {gAh, gAl, gBh, gBl};
    const int            rb[4]   = {row0, row0, col0, col0};

    auto issue_chunk = [&](int ch, int buf) {
        const int k0 = ch * CHUNK;
        const uint32_t sb = smem_u + buf * STAGE_B;
        #pragma unroll
        for (int t = 0; t < 4; t++)
            #pragma unroll
            for (int i = 0; i < 4; i++) {
                int id = tid + i * 128;           // 0..511 = 128 rows x 4
                int r = id >> 2, c16 = id & 3;
                cp16(sb + t * TILE_B + (uint32_t)(r * LDS_B + c16 * 16),
                     srcs[t] + (size_t)(rb[t] + r) * GK + k0 + c16 * 8);
            }
        CP_COMMIT();
    };

    issue_chunk(0, 0);
    for (int ch = 0; ch < NCH; ch++) {
        const int buf = ch & 1;
        if (ch + 1 < NCH) { issue_chunk(ch + 1, buf ^ 1); CP_WAIT1(); }
        else              { CP_WAIT0(); }
        __syncthreads();

        const uint32_t sb = smem_u + buf * STAGE_B;

        // ---- preload ALL B fragments for both ks halves (64 regs) ----
        uint32_t bh[2][8][2], bl[2][8][2];
        #pragma unroll
        for (int ks = 0; ks < 2; ks++) {
            const uint32_t kof = ks * 32;
            #pragma unroll
            for (int p = 0; p < 4; p++) {
                uint32_t t4[4];
                ldsm_x4(t4, sb + 2 * TILE_B + bCore + p * 16 * LDS_B + kof);
                bh[ks][2 * p][0] = t4[0]; bh[ks][2 * p][1] = t4[1];
                bh[ks][2 * p + 1][0] = t4[2]; bh[ks][2 * p + 1][1] = t4[3];
            }
        }
        #pragma unroll
        for (int ks = 0; ks < 2; ks++) {
            const uint32_t kof = ks * 32;
            #pragma unroll
            for (int p = 0; p < 4; p++) {
                uint32_t t4[4];
                ldsm_x4(t4, sb + 3 * TILE_B + bCore + p * 16 * LDS_B + kof);
                bl[ks][2 * p][0] = t4[0]; bl[ks][2 * p][1] = t4[1];
                bl[ks][2 * p + 1][0] = t4[2]; bl[ks][2 * p + 1][1] = t4[3];
            }
        }

        // ---- per mt: A-ldsm for both ks back-to-back, alternate MMA bursts ----
        #pragma unroll
        for (int mt = 0; mt < 4; mt++) {
            uint32_t ah0[4], ah1[4], al0[4], al1[4];
            ldsm_x4(ah0, sb + aCore + mt * 16 * LDS_B);
            ldsm_x4(ah1, sb + aCore + mt * 16 * LDS_B + 32);
            #pragma unroll
            for (int nt = 0; nt < 8; nt++) mma_bf16(acc[mt][nt], ah0, bh[0][nt]);
            #pragma unroll
            for (int nt = 0; nt < 8; nt++) mma_bf16(acc[mt][nt], ah1, bh[1][nt]);
            ldsm_x4(al0, sb + TILE_B + aCore + mt * 16 * LDS_B);
            ldsm_x4(al1, sb + TILE_B + aCore + mt * 16 * LDS_B + 32);
            #pragma unroll
            for (int nt = 0; nt < 8; nt++) mma_bf16(acc[mt][nt], ah0, bl[0][nt]);
            #pragma unroll
            for (int nt = 0; nt < 8; nt++) mma_bf16(acc[mt][nt], ah1, bl[1][nt]);
            #pragma unroll
            for (int nt = 0; nt < 8; nt++) mma_bf16(acc[mt][nt], al0, bh[0][nt]);
            #pragma unroll
            for (int nt = 0; nt < 8; nt++) mma_bf16(acc[mt][nt], al1, bh[1][nt]);
        }
        __syncthreads();
    }

    // -------- epilogue: optional write, then optional sumsq --------
    float aEff = alpha;
    if (alphaIdx >= 0) aEff *= g_scalars[alphaIdx];
    const int gid = lane >> 2, tig = lane & 3;
    const int rowBase = row0 + wm * 64;
    const int colBase = col0 + wn * 64;

    if (oF || oH) {
        #pragma unroll
        for (int mt = 0; mt < 4; mt++)
            #pragma unroll
            for (int nt = 0; nt < 8; nt++)
                #pragma unroll
                for (int h = 0; h < 2; h++) {
                    const int r  = rowBase + mt * 16 + gid + h * 8;
                    const int cc = colBase + nt * 8 + tig * 2;
                    const size_t ro = (size_t)r * GK + cc;
                    float v0 = aEff * acc[mt][nt][2 * h];
                    float v1 = aEff * acc[mt][nt][2 * h + 1];
                    if (dH) {
                        __nv_bfloat162 h2 = *reinterpret_cast<const __nv_bfloat162*>(dH + ro);
                        __nv_bfloat162 l2 = *reinterpret_cast<const __nv_bfloat162*>(dL + ro);
                        v0 += beta * (__bfloat162float(h2.x) + __bfloat162float(l2.x));
                        v1 += beta * (__bfloat162float(h2.y) + __bfloat162float(l2.y));
                    }
                    if (oF)
                        *reinterpret_cast<float2*>(oF + ro) = make_float2(v0, v1);
                    if (oH) {
                        __nv_bfloat16 h0 = __float2bfloat16(v0);
                        __nv_bfloat16 h1 = __float2bfloat16(v1);
                        __nv_bfloat16 l0 = __float2bfloat16(v0 - __bfloat162float(h0));
                        __nv_bfloat16 l1 = __float2bfloat16(v1 - __bfloat162float(h1));
                        *reinterpret_cast<__nv_bfloat162*>(oH + ro) = __halves2bfloat162(h0, h1);
                        *reinterpret_cast<__nv_bfloat162*>(oL + ro) = __halves2bfloat162(l0, l1);
                    }
                }
    }
    if (sumsq) {
        double s = 0.0;
        #pragma unroll
        for (int mt = 0; mt < 4; mt++)
            #pragma unroll
            for (int nt = 0; nt < 8; nt++)
                #pragma unroll
                for (int i = 0; i < 4; i++) {
                    float v = acc[mt][nt][i];
                    s += (double)v * (double)v;
                }
        #pragma unroll
        for (int o = 16; o > 0; o >>= 1) s += __shfl_down_sync(0xffffffffu, s, o);
        double* sred = reinterpret_cast<double*>(smem_raw);
        __syncthreads();
        if (lane == 0) sred[wid] = s;
        __syncthreads();
        if (wid == 0) {
            s = (lane < 4) ? sred[lane] : 0.0;
            #pragma unroll
            for (int o = 2; o > 0; o >>= 1) s += __shfl_down_sync(0xffffffffu, s, o);
            if (lane == 0) atomicAdd(&g_accum, s);
        }
    }
}

// ============================================================================
// Elementwise kernels
// ============================================================================
__global__ void zero_accum_kernel() { g_accum = 0.0; }

__global__ void finalize_kernel(const float* __restrict__ gamma)
{
    double fro2   = g_accum;                   // ||M^2||_F^2 (same spectrum as wwt)
    double w_norm = pow(fro2, 0.125) + 1e-8;
    g_scalars[0] = (float)w_norm;
    g_scalars[1] = (float)(1.0 / w_norm);
    g_scalars[2] = (float)w_norm * gamma[0];
    double s2 = 1.0 / (w_norm * w_norm);
    g_scalars[3] = (float)s2;
    g_scalars[4] = (float)(s2 * s2);
}

__global__ void split_kernel(const float* __restrict__ src,
                             __nv_bfloat16* __restrict__ dHo,
                             __nv_bfloat16* __restrict__ dLo, int scaleIdx)
{
    float s = (scaleIdx >= 0) ? g_scalars[scaleIdx] : 1.0f;
    size_t i = ((size_t)blockIdx.x * 256 + threadIdx.x) * 4;
    float4 v = *reinterpret_cast<const float4*>(src + i);
    float f[4] = {v.x * s, v.y * s, v.z * s, v.w * s};
    __nv_bfloat16 h[4], l[4];
    #pragma unroll
    for (int j = 0; j < 4; j++) {
        h[j] = __float2bfloat16(f[j]);
        l[j] = __float2bfloat16(f[j] - __bfloat162float(h[j]));
    }
    *reinterpret_cast<__nv_bfloat162*>(dHo + i)     = __halves2bfloat162(h[0], h[1]);
    *reinterpret_cast<__nv_bfloat162*>(dHo + i + 2) = __halves2bfloat162(h[2], h[3]);
    *reinterpret_cast<__nv_bfloat162*>(dLo + i)     = __halves2bfloat162(l[0], l[1]);
    *reinterpret_cast<__nv_bfloat162*>(dLo + i + 2) = __halves2bfloat162(l[2], l[3]);
}

// T0 = (c/w_norm^4)*M2 + (b/w_norm^2)*M ; M2 lives in (Eh,El), M in (Mh,Ml);
// result overwrites (Eh,El) as a hi/lo pair.
__global__ void t0_combine_kernel(const __nv_bfloat16* __restrict__ Mh,
                                  const __nv_bfloat16* __restrict__ Ml,
                                  __nv_bfloat16* __restrict__ Eh,
                                  __nv_bfloat16* __restrict__ El,
                                  float b, float c)
{
    const float cb = c * g_scalars[4];
    const float bb = b * g_scalars[3];
    size_t i = ((size_t)blockIdx.x * 256 + threadIdx.x) * 2;
    __nv_bfloat162 m2h = *reinterpret_cast<const __nv_bfloat162*>(Eh + i);
    __nv_bfloat162 m2l = *reinterpret_cast<const __nv_bfloat162*>(El + i);
    __nv_bfloat162 mh  = *reinterpret_cast<const __nv_bfloat162*>(Mh + i);
    __nv_bfloat162 ml  = *reinterpret_cast<const __nv_bfloat162*>(Ml + i);
    float v0 = cb * (__bfloat162float(m2h.x) + __bfloat162float(m2l.x))
             + bb * (__bfloat162float(mh.x)  + __bfloat162float(ml.x));
    float v1 = cb * (__bfloat162float(m2h.y) + __bfloat162float(m2l.y))
             + bb * (__bfloat162float(mh.y)  + __bfloat162float(ml.y));
    __nv_bfloat16 h0 = __float2bfloat16(v0);
    __nv_bfloat16 h1 = __float2bfloat16(v1);
    __nv_bfloat16 l0 = __float2bfloat16(v0 - __bfloat162float(h0));
    __nv_bfloat16 l1 = __float2bfloat16(v1 - __bfloat162float(h1));
    *reinterpret_cast<__nv_bfloat162*>(Eh + i) = __halves2bfloat162(h0, h1);
    *reinterpret_cast<__nv_bfloat162*>(El + i) = __halves2bfloat162(l0, l1);
}

// transpose a 2048x2048 bf16 matrix pair (z=0: hi, z=1: lo), 64x64 tiles
__global__ void transpose_kernel(const __nv_bfloat16* __restrict__ sH,
                                 const __nv_bfloat16* __restrict__ sL,
                                 __nv_bfloat16* __restrict__ dHo,
                                 __nv_bfloat16* __restrict__ dLo)
{
    __shared__ uint32_t tsm[64][33];
    const __nv_bfloat16* src = blockIdx.z ? sL : sH;
    __nv_bfloat16*       dst = blockIdx.z ? dLo : dHo;
    const int r0 = blockIdx.y * 64, c0 = blockIdx.x * 64;
    const int t = threadIdx.x;
    const int x2 = t & 31, y0 = t >> 5;
    for (int yy = y0; yy < 64; yy += 8)
        tsm[yy][x2] = *reinterpret_cast<const uint32_t*>(
            src + (size_t)(r0 + yy) * GK + c0 + x2 * 2);
    __syncthreads();
    for (int idx = t; idx < 64 * 32; idx += 256) {
        int n = idx >> 5, jp = idx & 31;
        uint32_t a = tsm[2 * jp][n >> 1];
        uint32_t b = tsm[2 * jp + 1][n >> 1];
        uint32_t lo = (n & 1) ? (a >> 16) : (a & 0xffffu);
        uint32_t hi = (n & 1) ? (b >> 16) : (b & 0xffffu);
        *reinterpret_cast<uint32_t*>(dst + (size_t)(c0 + n) * GK + r0 + 2 * jp) =
            lo | (hi << 16);
    }
}

// ============================================================================
// Host orchestration (graph-capturable: kernel launches only)
// ============================================================================
static const float PE_COEF[8][3] = {
    {7.2086f, -15.5131f, 9.0178f}, {3.9623f, -2.5813f, 0.4542f},
    {3.9466f, -2.5765f, 0.4544f}, {3.8991f, -2.5671f, 0.4566f},
    {3.7186f, -2.5308f, 0.4653f}, {3.1390f, -2.3073f, 0.4733f},
    {2.1715f, -1.5246f, 0.3885f}, {1.8648f, -1.2224f, 0.3577f},
};

struct BPtr { __nv_bfloat16 *h, *l; };

static inline void run_gemm(int Mrows, BPtr A, BPtr B,
                            BPtr out, float* oF, BPtr D,
                            float alpha, float beta, int alphaIdx, int sumsq)
{
    cudaFuncSetAttribute(gemm_bf16x3_kernel,
                         cudaFuncAttributeMaxDynamicSharedMemorySize, SMEM_NEED);
    dim3 grid(GK / 128, Mrows / 128), block(128);
    gemm_bf16x3_kernel<<<grid, block, SMEM_NEED>>>(
        A.h, A.l, B.h, B.l, out.h, out.l, oF, D.h, D.l,
        alpha, beta, alphaIdx, sumsq);
}

extern "C" void kernel_launch(void* const* d_in, const int* in_sizes, int n_in,
                              void* d_out, int out_size)
{
    const float* x      = (const float*)d_in[0];
    const float* weight = (const float*)d_in[1];
    const float* gamma  = (const float*)d_in[2];
    float*       out    = (float*)d_out;
    const int M_out = in_sizes[0] / GK;      // 8192

    auto sym = [](const void* s) {
        void* p; cudaGetSymbolAddress(&p, s); return (__nv_bfloat16*)p;
    };
    BPtr w  = {sym(g_wh),  sym(g_wl)};
    BPtr u0 = {sym(g_u0h), sym(g_u0l)};
    BPtr u1 = {sym(g_u1h), sym(g_u1l)};
    BPtr t0 = {sym(g_t0h), sym(g_t0l)};
    BPtr t1 = {sym(g_t1h), sym(g_t1l)};
    BPtr g  = {sym(g_gh),  sym(g_gl)};
    BPtr e  = {sym(g_eh),  sym(g_el)};
    BPtr X  = {sym(g_xh),  sym(g_xl)};
    BPtr nil = {nullptr, nullptr};

    const dim3 tgrid(32, 32, 2);

    // ---- M = W^T W ; w_norm = ||M^2||_F^0.25 + eps (same spectrum as W W^T) ----
    zero_accum_kernel<<<1, 1>>>();
    split_kernel<<<MAT / 4 / 256, 256>>>(weight, w.h, w.l, -1);
    transpose_kernel<<<tgrid, 256>>>(w.h, w.l, t0.h, t0.l);            // wt
    run_gemm(GK, t0, t0, g, nullptr, nil, 1.0f, 0.0f, -1, 0);          // M -> g
    run_gemm(GK, g, g, e, nullptr, nil, 1.0f, 0.0f, -1, 1);            // M^2 -> e, + sumsq
    finalize_kernel<<<1, 1>>>(gamma);

    // ---- U0 = W / w_norm ; X split ----
    split_kernel<<<MAT / 4 / 256, 256>>>(weight, u0.h, u0.l, 1);
    split_kernel<<<XMAT / 4 / 256, 256>>>(x, X.h, X.l, -1);

    // ---- 8 Polar Express iterations (it 0: g,T are elementwise from M,M^2) ----
    BPtr U = u0, Un = u1, UT = t0, UTn = t1;
    for (int it = 0; it < 8; it++) {
        float a = PE_COEF[it][0], bb = PE_COEF[it][1], c = PE_COEF[it][2];
        if (it == 0) {
            // e <- (c/w_norm^4)*M^2 + (b/w_norm^2)*M   (M in g, M^2 in e)
            t0_combine_kernel<<<MAT / 2 / 256, 256>>>(g.h, g.l, e.h, e.l, bb, c);
        } else {
            run_gemm(GK, UT, UT, g, nullptr, nil, 1.0f, 0.0f, -1, 0);  // g = U^T U
            run_gemm(GK, g,  g,  e, nullptr, g,   c,    bb,   -1, 0);  // T = c g^2 + b g
        }
        run_gemm(GK, U, e, Un, nullptr, U, 1.0f, a, -1, 0);            // Un = U T + a U
        if (it < 7)
            transpose_kernel<<<tgrid, 256>>>(Un.h, Un.l, UTn.h, UTn.l);
        BPtr tp;
        tp = U; U = Un; Un = tp;
        tp = UT; UT = UTn; UTn = tp;
    }

    // ---- out = (w_norm * gamma) * X @ U^T ----
    run_gemm(M_out, X, U, nil, out, nil, 1.0f, 0.0f, 2, 0);
}

// round 16
// speedup vs baseline: 1.0502x; 1.0502x over previous
#include <cuda_runtime.h>
#include <cuda_bf16.h>
#include <math.h>
#include <stdint.h>

// ============================================================================
// PCLinear via mma.sync bf16x3 (hi/lo split, 3-term compensated product).
// R16 = R14 (iteration-0 algebraic elimination; CTA 128x128, 4 warps 2x2,
// warp tile 64x64, CHUNK 32, LDS_B 80, occupancy 2) with ONE change:
// per mt, `ldsm al` issues immediately after `ldsm ah` so its latency hides
// behind the 16 ah-MMAs (R15 lesson: keep extra live regs minimal).
// ============================================================================

#define GK     2048
#define MAT    (GK * GK)
#define XROWS  8192
#define XMAT   (XROWS * GK)

#define CHUNK    32
#define NCH      (GK / CHUNK)       // 64
#define LDS_B    80                 // smem row stride (40 bf16): conflict-free ldsm
#define TILE_B   (128 * LDS_B)      // 10240 per tile
#define STAGE_B  (4 * TILE_B)       // Ah, Al, Bh, Bl
#define SMEM_NEED (1024 + 2 * STAGE_B)   // ~83KB -> 2 CTAs/SM

// -------------------- device scratch (static, no allocs) --------------------
__device__ __nv_bfloat16 g_wh[MAT],  g_wl[MAT];
__device__ __nv_bfloat16 g_u0h[MAT], g_u0l[MAT];
__device__ __nv_bfloat16 g_u1h[MAT], g_u1l[MAT];
__device__ __nv_bfloat16 g_t0h[MAT], g_t0l[MAT];
__device__ __nv_bfloat16 g_t1h[MAT], g_t1l[MAT];
__device__ __nv_bfloat16 g_gh[MAT],  g_gl[MAT];
__device__ __nv_bfloat16 g_eh[MAT],  g_el[MAT];
__device__ __nv_bfloat16 g_xh[XMAT], g_xl[XMAT];
__device__ double g_accum;
__device__ float  g_scalars[5];
// [0]=w_norm [1]=1/w_norm [2]=w_norm*gamma [3]=1/w_norm^2 [4]=1/w_norm^4

// -------------------- low-level helpers --------------------
__device__ __forceinline__ uint32_t smem_to_u32(const void* p) {
    uint32_t a;
    asm("{ .reg .u64 t; cvta.to.shared.u64 t, %1; cvt.u32.u64 %0, t; }"
        : "=r"(a) : "l"(p));
    return a;
}
__device__ __forceinline__ void ldsm_x4(uint32_t* r, uint32_t addr) {
    asm volatile("ldmatrix.sync.aligned.m8n8.x4.shared.b16 {%0,%1,%2,%3}, [%4];"
                 : "=r"(r[0]), "=r"(r[1]), "=r"(r[2]), "=r"(r[3]) : "r"(addr));
}
__device__ __forceinline__ void mma_bf16(float* c, const uint32_t* a, const uint32_t* b) {
    asm volatile("mma.sync.aligned.m16n8k16.row.col.f32.bf16.bf16.f32 "
                 "{%0,%1,%2,%3}, {%4,%5,%6,%7}, {%8,%9}, {%0,%1,%2,%3};"
                 : "+f"(c[0]), "+f"(c[1]), "+f"(c[2]), "+f"(c[3])
                 : "r"(a[0]), "r"(a[1]), "r"(a[2]), "r"(a[3]),
                   "r"(b[0]), "r"(b[1]));
}
__device__ __forceinline__ void cp16(uint32_t dst, const void* src) {
    asm volatile("cp.async.cg.shared.global [%0], [%1], 16;" :: "r"(dst), "l"(src));
}
#define CP_COMMIT() asm volatile("cp.async.commit_group;" ::: "memory")
#define CP_WAIT1()  asm volatile("cp.async.wait_group 1;" ::: "memory")
#define CP_WAIT0()  asm volatile("cp.async.wait_group 0;" ::: "memory")

// ============================================================================
// bf16x3 GEMM: C[m,n] = alphaEff * sum_k (Ah+Al)[m,k]*(Bh+Bl)[n,k]
//              (+ beta*(Dh+Dl)); writes bf16 hi/lo (oH/oL) and/or fp32 (oF);
//              sumsq!=0 ALSO accumulates ||raw acc||_F^2 into g_accum.
// CTA 128x128, 4 warps (2x2), warp tile 64x64, K-chunk 32, 128 threads.
// ============================================================================
__global__ __launch_bounds__(128, 2)
void gemm_bf16x3_kernel(const __nv_bfloat16* __restrict__ gAh,
                        const __nv_bfloat16* __restrict__ gAl,
                        const __nv_bfloat16* __restrict__ gBh,
                        const __nv_bfloat16* __restrict__ gBl,
                        __nv_bfloat16* __restrict__ oH,
                        __nv_bfloat16* __restrict__ oL,
                        float* __restrict__ oF,
                        const __nv_bfloat16* __restrict__ dH,
                        const __nv_bfloat16* __restrict__ dL,
                        float alpha, float beta, int alphaIdx, int sumsq)
{
    extern __shared__ char smem_raw[];
    const uint32_t smem_u = (smem_to_u32(smem_raw) + 1023u) & ~1023u;

    const int tid  = threadIdx.x;
    const int wid  = tid >> 5;
    const int lane = tid & 31;
    const int wm   = wid >> 1;        // 0..1 (64-row half)
    const int wn   = wid & 1;         // 0..1 (64-col half)
    const int row0 = blockIdx.y * 128;
    const int col0 = blockIdx.x * 128;

    const uint32_t aCore = (uint32_t)(wm * 64 * LDS_B + (lane & 15) * LDS_B
                                      + (lane >> 4) * 16);
    const uint32_t bCore = (uint32_t)(wn * 64 * LDS_B + (lane & 7) * LDS_B
                                      + ((lane >> 3) & 1) * 16
                                      + ((lane >> 4) & 1) * 8 * LDS_B);

    float acc[4][8][4];
    #pragma unroll
    for (int mt = 0; mt < 4; mt++)
        #pragma unroll
        for (int nt = 0; nt < 8; nt++)
            #pragma unroll
            for (int i = 0; i < 4; i++) acc[mt][nt][i] = 0.0f;

    const __nv_bfloat16* srcs[4] = {gAh, gAl, gBh, gBl};
    const int            rb[4]   = {row0, row0, col0, col0};

    auto issue_chunk = [&](int ch, int buf) {
        const int k0 = ch * CHUNK;
        const uint32_t sb = smem_u + buf * STAGE_B;
        #pragma unroll
        for (int t = 0; t < 4; t++)
            #pragma unroll
            for (int i = 0; i < 4; i++) {
                int id = tid + i * 128;           // 0..511 = 128 rows x 4
                int r = id >> 2, c16 = id & 3;
                cp16(sb + t * TILE_B + (uint32_t)(r * LDS_B + c16 * 16),
                     srcs[t] + (size_t)(rb[t] + r) * GK + k0 + c16 * 8);
            }
        CP_COMMIT();
    };

    issue_chunk(0, 0);
    for (int ch = 0; ch < NCH; ch++) {
        const int buf = ch & 1;
        if (ch + 1 < NCH) { issue_chunk(ch + 1, buf ^ 1); CP_WAIT1(); }
        else              { CP_WAIT0(); }
        __syncthreads();

        const uint32_t sb = smem_u + buf * STAGE_B;
        #pragma unroll
        for (int ks = 0; ks < 2; ks++) {
            const uint32_t kof = ks * 32;
            uint32_t bh[8][2], bl[8][2];
            #pragma unroll
            for (int p = 0; p < 4; p++) {
                uint32_t t4[4];
                ldsm_x4(t4, sb + 2 * TILE_B + bCore + p * 16 * LDS_B + kof);
                bh[2 * p][0] = t4[0]; bh[2 * p][1] = t4[1];
                bh[2 * p + 1][0] = t4[2]; bh[2 * p + 1][1] = t4[3];
            }
            #pragma unroll
            for (int p = 0; p < 4; p++) {
                uint32_t t4[4];
                ldsm_x4(t4, sb + 3 * TILE_B + bCore + p * 16 * LDS_B + kof);
                bl[2 * p][0] = t4[0]; bl[2 * p][1] = t4[1];
                bl[2 * p + 1][0] = t4[2]; bl[2 * p + 1][1] = t4[3];
            }
            #pragma unroll
            for (int mt = 0; mt < 4; mt++) {
                uint32_t ah[4], al[4];
                // R16 change: issue BOTH A-ldsm up front; al's latency hides
                // behind the 16 ah-MMAs below.
                ldsm_x4(ah, sb + aCore + mt * 16 * LDS_B + kof);
                ldsm_x4(al, sb + TILE_B + aCore + mt * 16 * LDS_B + kof);
                #pragma unroll
                for (int nt = 0; nt < 8; nt++) mma_bf16(acc[mt][nt], ah, bh[nt]);
                #pragma unroll
                for (int nt = 0; nt < 8; nt++) mma_bf16(acc[mt][nt], ah, bl[nt]);
                #pragma unroll
                for (int nt = 0; nt < 8; nt++) mma_bf16(acc[mt][nt], al, bh[nt]);
            }
        }
        __syncthreads();
    }

    // -------- epilogue: optional write, then optional sumsq --------
    float aEff = alpha;
    if (alphaIdx >= 0) aEff *= g_scalars[alphaIdx];
    const int gid = lane >> 2, tig = lane & 3;
    const int rowBase = row0 + wm * 64;
    const int colBase = col0 + wn * 64;

    if (oF || oH) {
        #pragma unroll
        for (int mt = 0; mt < 4; mt++)
            #pragma unroll
            for (int nt = 0; nt < 8; nt++)
                #pragma unroll
                for (int h = 0; h < 2; h++) {
                    const int r  = rowBase + mt * 16 + gid + h * 8;
                    const int cc = colBase + nt * 8 + tig * 2;
                    const size_t ro = (size_t)r * GK + cc;
                    float v0 = aEff * acc[mt][nt][2 * h];
                    float v1 = aEff * acc[mt][nt][2 * h + 1];
                    if (dH) {
                        __nv_bfloat162 h2 = *reinterpret_cast<const __nv_bfloat162*>(dH + ro);
                        __nv_bfloat162 l2 = *reinterpret_cast<const __nv_bfloat162*>(dL + ro);
                        v0 += beta * (__bfloat162float(h2.x) + __bfloat162float(l2.x));
                        v1 += beta * (__bfloat162float(h2.y) + __bfloat162float(l2.y));
                    }
                    if (oF)
                        *reinterpret_cast<float2*>(oF + ro) = make_float2(v0, v1);
                    if (oH) {
                        __nv_bfloat16 h0 = __float2bfloat16(v0);
                        __nv_bfloat16 h1 = __float2bfloat16(v1);
                        __nv_bfloat16 l0 = __float2bfloat16(v0 - __bfloat162float(h0));
                        __nv_bfloat16 l1 = __float2bfloat16(v1 - __bfloat162float(h1));
                        *reinterpret_cast<__nv_bfloat162*>(oH + ro) = __halves2bfloat162(h0, h1);
                        *reinterpret_cast<__nv_bfloat162*>(oL + ro) = __halves2bfloat162(l0, l1);
                    }
                }
    }
    if (sumsq) {
        double s = 0.0;
        #pragma unroll
        for (int mt = 0; mt < 4; mt++)
            #pragma unroll
            for (int nt = 0; nt < 8; nt++)
                #pragma unroll
                for (int i = 0; i < 4; i++) {
                    float v = acc[mt][nt][i];
                    s += (double)v * (double)v;
                }
        #pragma unroll
        for (int o = 16; o > 0; o >>= 1) s += __shfl_down_sync(0xffffffffu, s, o);
        double* sred = reinterpret_cast<double*>(smem_raw);
        __syncthreads();
        if (lane == 0) sred[wid] = s;
        __syncthreads();
        if (wid == 0) {
            s = (lane < 4) ? sred[lane] : 0.0;
            #pragma unroll
            for (int o = 2; o > 0; o >>= 1) s += __shfl_down_sync(0xffffffffu, s, o);
            if (lane == 0) atomicAdd(&g_accum, s);
        }
    }
}

// ============================================================================
// Elementwise kernels
// ============================================================================
__global__ void zero_accum_kernel() { g_accum = 0.0; }

__global__ void finalize_kernel(const float* __restrict__ gamma)
{
    double fro2   = g_accum;                   // ||M^2||_F^2 (same spectrum as wwt)
    double w_norm = pow(fro2, 0.125) + 1e-8;
    g_scalars[0] = (float)w_norm;
    g_scalars[1] = (float)(1.0 / w_norm);
    g_scalars[2] = (float)w_norm * gamma[0];
    double s2 = 1.0 / (w_norm * w_norm);
    g_scalars[3] = (float)s2;
    g_scalars[4] = (float)(s2 * s2);
}

__global__ void split_kernel(const float* __restrict__ src,
                             __nv_bfloat16* __restrict__ dHo,
                             __nv_bfloat16* __restrict__ dLo, int scaleIdx)
{
    float s = (scaleIdx >= 0) ? g_scalars[scaleIdx] : 1.0f;
    size_t i = ((size_t)blockIdx.x * 256 + threadIdx.x) * 4;
    float4 v = *reinterpret_cast<const float4*>(src + i);
    float f[4] = {v.x * s, v.y * s, v.z * s, v.w * s};
    __nv_bfloat16 h[4], l[4];
    #pragma unroll
    for (int j = 0; j < 4; j++) {
        h[j] = __float2bfloat16(f[j]);
        l[j] = __float2bfloat16(f[j] - __bfloat162float(h[j]));
    }
    *reinterpret_cast<__nv_bfloat162*>(dHo + i)     = __halves2bfloat162(h[0], h[1]);
    *reinterpret_cast<__nv_bfloat162*>(dHo + i + 2) = __halves2bfloat162(h[2], h[3]);
    *reinterpret_cast<__nv_bfloat162*>(dLo + i)     = __halves2bfloat162(l[0], l[1]);
    *reinterpret_cast<__nv_bfloat162*>(dLo + i + 2) = __halves2bfloat162(l[2], l[3]);
}

// T0 = (c/w_norm^4)*M2 + (b/w_norm^2)*M ; M2 lives in (Eh,El), M in (Mh,Ml);
// result overwrites (Eh,El) as a hi/lo pair.
__global__ void t0_combine_kernel(const __nv_bfloat16* __restrict__ Mh,
                                  const __nv_bfloat16* __restrict__ Ml,
                                  __nv_bfloat16* __restrict__ Eh,
                                  __nv_bfloat16* __restrict__ El,
                                  float b, float c)
{
    const float cb = c * g_scalars[4];
    const float bb = b * g_scalars[3];
    size_t i = ((size_t)blockIdx.x * 256 + threadIdx.x) * 2;
    __nv_bfloat162 m2h = *reinterpret_cast<const __nv_bfloat162*>(Eh + i);
    __nv_bfloat162 m2l = *reinterpret_cast<const __nv_bfloat162*>(El + i);
    __nv_bfloat162 mh  = *reinterpret_cast<const __nv_bfloat162*>(Mh + i);
    __nv_bfloat162 ml  = *reinterpret_cast<const __nv_bfloat162*>(Ml + i);
    float v0 = cb * (__bfloat162float(m2h.x) + __bfloat162float(m2l.x))
             + bb * (__bfloat162float(mh.x)  + __bfloat162float(ml.x));
    float v1 = cb * (__bfloat162float(m2h.y) + __bfloat162float(m2l.y))
             + bb * (__bfloat162float(mh.y)  + __bfloat162float(ml.y));
    __nv_bfloat16 h0 = __float2bfloat16(v0);
    __nv_bfloat16 h1 = __float2bfloat16(v1);
    __nv_bfloat16 l0 = __float2bfloat16(v0 - __bfloat162float(h0));
    __nv_bfloat16 l1 = __float2bfloat16(v1 - __bfloat162float(h1));
    *reinterpret_cast<__nv_bfloat162*>(Eh + i) = __halves2bfloat162(h0, h1);
    *reinterpret_cast<__nv_bfloat162*>(El + i) = __halves2bfloat162(l0, l1);
}

// transpose a 2048x2048 bf16 matrix pair (z=0: hi, z=1: lo), 64x64 tiles
__global__ void transpose_kernel(const __nv_bfloat16* __restrict__ sH,
                                 const __nv_bfloat16* __restrict__ sL,
                                 __nv_bfloat16* __restrict__ dHo,
                                 __nv_bfloat16* __restrict__ dLo)
{
    __shared__ uint32_t tsm[64][33];
    const __nv_bfloat16* src = blockIdx.z ? sL : sH;
    __nv_bfloat16*       dst = blockIdx.z ? dLo : dHo;
    const int r0 = blockIdx.y * 64, c0 = blockIdx.x * 64;
    const int t = threadIdx.x;
    const int x2 = t & 31, y0 = t >> 5;
    for (int yy = y0; yy < 64; yy += 8)
        tsm[yy][x2] = *reinterpret_cast<const uint32_t*>(
            src + (size_t)(r0 + yy) * GK + c0 + x2 * 2);
    __syncthreads();
    for (int idx = t; idx < 64 * 32; idx += 256) {
        int n = idx >> 5, jp = idx & 31;
        uint32_t a = tsm[2 * jp][n >> 1];
        uint32_t b = tsm[2 * jp + 1][n >> 1];
        uint32_t lo = (n & 1) ? (a >> 16) : (a & 0xffffu);
        uint32_t hi = (n & 1) ? (b >> 16) : (b & 0xffffu);
        *reinterpret_cast<uint32_t*>(dst + (size_t)(c0 + n) * GK + r0 + 2 * jp) =
            lo | (hi << 16);
    }
}

// ============================================================================
// Host orchestration (graph-capturable: kernel launches only)
// ============================================================================
static const float PE_COEF[8][3] = {
    {7.2086f, -15.5131f, 9.0178f}, {3.9623f, -2.5813f, 0.4542f},
    {3.9466f, -2.5765f, 0.4544f}, {3.8991f, -2.5671f, 0.4566f},
    {3.7186f, -2.5308f, 0.4653f}, {3.1390f, -2.3073f, 0.4733f},
    {2.1715f, -1.5246f, 0.3885f}, {1.8648f, -1.2224f, 0.3577f},
};

struct BPtr { __nv_bfloat16 *h, *l; };

static inline void run_gemm(int Mrows, BPtr A, BPtr B,
                            BPtr out, float* oF, BPtr D,
                            float alpha, float beta, int alphaIdx, int sumsq)
{
    cudaFuncSetAttribute(gemm_bf16x3_kernel,
                         cudaFuncAttributeMaxDynamicSharedMemorySize, SMEM_NEED);
    dim3 grid(GK / 128, Mrows / 128), block(128);
    gemm_bf16x3_kernel<<<grid, block, SMEM_NEED>>>(
        A.h, A.l, B.h, B.l, out.h, out.l, oF, D.h, D.l,
        alpha, beta, alphaIdx, sumsq);
}

extern "C" void kernel_launch(void* const* d_in, const int* in_sizes, int n_in,
                              void* d_out, int out_size)
{
    const float* x      = (const float*)d_in[0];
    const float* weight = (const float*)d_in[1];
    const float* gamma  = (const float*)d_in[2];
    float*       out    = (float*)d_out;
    const int M_out = in_sizes[0] / GK;      // 8192

    auto sym = [](const void* s) {
        void* p; cudaGetSymbolAddress(&p, s); return (__nv_bfloat16*)p;
    };
    BPtr w  = {sym(g_wh),  sym(g_wl)};
    BPtr u0 = {sym(g_u0h), sym(g_u0l)};
    BPtr u1 = {sym(g_u1h), sym(g_u1l)};
    BPtr t0 = {sym(g_t0h), sym(g_t0l)};
    BPtr t1 = {sym(g_t1h), sym(g_t1l)};
    BPtr g  = {sym(g_gh),  sym(g_gl)};
    BPtr e  = {sym(g_eh),  sym(g_el)};
    BPtr X  = {sym(g_xh),  sym(g_xl)};
    BPtr nil = {nullptr, nullptr};

    const dim3 tgrid(32, 32, 2);

    // ---- M = W^T W ; w_norm = ||M^2||_F^0.25 + eps (same spectrum as W W^T) ----
    zero_accum_kernel<<<1, 1>>>();
    split_kernel<<<MAT / 4 / 256, 256>>>(weight, w.h, w.l, -1);
    transpose_kernel<<<tgrid, 256>>>(w.h, w.l, t0.h, t0.l);            // wt
    run_gemm(GK, t0, t0, g, nullptr, nil, 1.0f, 0.0f, -1, 0);          // M -> g
    run_gemm(GK, g, g, e, nullptr, nil, 1.0f, 0.0f, -1, 1);            // M^2 -> e, + sumsq
    finalize_kernel<<<1, 1>>>(gamma);

    // ---- U0 = W / w_norm ; X split ----
    split_kernel<<<MAT / 4 / 256, 256>>>(weight, u0.h, u0.l, 1);
    split_kernel<<<XMAT / 4 / 256, 256>>>(x, X.h, X.l, -1);

    // ---- 8 Polar Express iterations (it 0: g,T are elementwise from M,M^2) ----
    BPtr U = u0, Un = u1, UT = t0, UTn = t1;
    for (int it = 0; it < 8; it++) {
        float a = PE_COEF[it][0], bb = PE_COEF[it][1], c = PE_COEF[it][2];
        if (it == 0) {
            // e <- (c/w_norm^4)*M^2 + (b/w_norm^2)*M   (M in g, M^2 in e)
            t0_combine_kernel<<<MAT / 2 / 256, 256>>>(g.h, g.l, e.h, e.l, bb, c);
        } else {
            run_gemm(GK, UT, UT, g, nullptr, nil, 1.0f, 0.0f, -1, 0);  // g = U^T U
            run_gemm(GK, g,  g,  e, nullptr, g,   c,    bb,   -1, 0);  // T = c g^2 + b g
        }
        run_gemm(GK, U, e, Un, nullptr, U, 1.0f, a, -1, 0);            // Un = U T + a U
        if (it < 7)
            transpose_kernel<<<tgrid, 256>>>(Un.h, Un.l, UTn.h, UTn.l);
        BPtr tp;
        tp = U; U = Un; Un = tp;
        tp = UT; UT = UTn; UTn = tp;
    }

    // ---- out = (w_norm * gamma) * X @ U^T ----
    run_gemm(M_out, X, U, nil, out, nil, 1.0f, 0.0f, 2, 0);
}

// round 17
// speedup vs baseline: 1.1004x; 1.0477x over previous
#include <cuda_runtime.h>
#include <cuda_bf16.h>
#include <math.h>
#include <stdint.h>

// ============================================================================
// PCLinear via mma.sync bf16x3 (hi/lo split, 3-term compensated product).
// R17 = R14 winner + TRA-mode GEMM using ldmatrix.trans: UtU / WtW are
// computed DIRECTLY from row-major U / W (k-major smem tiles, .trans ldsm for
// both fragments). All 9 transpose launches and the UT buffers are gone.
// ============================================================================

#define GK     2048
#define MAT    (GK * GK)
#define XROWS  8192
#define XMAT   (XROWS * GK)

#define CHUNK    32
#define NCH      (GK / CHUNK)       // 64
// --- row-major (non-TRA) tiles ---
#define LDS_B    80                 // 32B data + pad: conflict-free ldsm
#define TILE_B   (128 * LDS_B)      // 10240
#define STAGE_B  (4 * TILE_B)
// --- k-major (TRA) tiles: 32 k-rows x 128 cols (256B) + 16B pad ---
#define TSTR     272
#define TILE_T   (32 * TSTR)        // 8704
#define STAGE_T  (4 * TILE_T)       // 34816
#define SMEM_NEED (1024 + 2 * STAGE_B)   // max of both modes; ~83KB -> occ 2

// -------------------- device scratch (static, no allocs) --------------------
__device__ __nv_bfloat16 g_wh[MAT],  g_wl[MAT];
__device__ __nv_bfloat16 g_u0h[MAT], g_u0l[MAT];
__device__ __nv_bfloat16 g_u1h[MAT], g_u1l[MAT];
__device__ __nv_bfloat16 g_gh[MAT],  g_gl[MAT];
__device__ __nv_bfloat16 g_eh[MAT],  g_el[MAT];
__device__ __nv_bfloat16 g_xh[XMAT], g_xl[XMAT];
__device__ double g_accum;
__device__ float  g_scalars[5];
// [0]=w_norm [1]=1/w_norm [2]=w_norm*gamma [3]=1/w_norm^2 [4]=1/w_norm^4

// -------------------- low-level helpers --------------------
__device__ __forceinline__ uint32_t smem_to_u32(const void* p) {
    uint32_t a;
    asm("{ .reg .u64 t; cvta.to.shared.u64 t, %1; cvt.u32.u64 %0, t; }"
        : "=r"(a) : "l"(p));
    return a;
}
__device__ __forceinline__ void ldsm_x4(uint32_t* r, uint32_t addr) {
    asm volatile("ldmatrix.sync.aligned.m8n8.x4.shared.b16 {%0,%1,%2,%3}, [%4];"
                 : "=r"(r[0]), "=r"(r[1]), "=r"(r[2]), "=r"(r[3]) : "r"(addr));
}
__device__ __forceinline__ void ldsm_x4_t(uint32_t* r, uint32_t addr) {
    asm volatile("ldmatrix.sync.aligned.m8n8.x4.trans.shared.b16 {%0,%1,%2,%3}, [%4];"
                 : "=r"(r[0]), "=r"(r[1]), "=r"(r[2]), "=r"(r[3]) : "r"(addr));
}
__device__ __forceinline__ void mma_bf16(float* c, const uint32_t* a, const uint32_t* b) {
    asm volatile("mma.sync.aligned.m16n8k16.row.col.f32.bf16.bf16.f32 "
                 "{%0,%1,%2,%3}, {%4,%5,%6,%7}, {%8,%9}, {%0,%1,%2,%3};"
                 : "+f"(c[0]), "+f"(c[1]), "+f"(c[2]), "+f"(c[3])
                 : "r"(a[0]), "r"(a[1]), "r"(a[2]), "r"(a[3]),
                   "r"(b[0]), "r"(b[1]));
}
__device__ __forceinline__ void cp16(uint32_t dst, const void* src) {
    asm volatile("cp.async.cg.shared.global [%0], [%1], 16;" :: "r"(dst), "l"(src));
}
#define CP_COMMIT() asm volatile("cp.async.commit_group;" ::: "memory")
#define CP_WAIT1()  asm volatile("cp.async.wait_group 1;" ::: "memory")
#define CP_WAIT0()  asm volatile("cp.async.wait_group 0;" ::: "memory")

// ============================================================================
// bf16x3 GEMM.
//  TRA=0: C[m,n] = sum_k A[row0+m, k] * B[col0+n, k]   (A,B row-major, k-contig)
//  TRA=1: C[m,n] = sum_k S[k, row0+m] * S[k, col0+n]   (S row-major; k-major
//         tiles + .trans ldsm -> computes S^T S with NO transposed copy)
//  + beta*(Dh+Dl); writes bf16 hi/lo and/or fp32; sumsq -> g_accum.
// CTA 128x128, 4 warps (2x2), warp tile 64x64, K-chunk 32, 128 threads.
// ============================================================================
template<int TRA>
__global__ __launch_bounds__(128, 2)
void gemm_bf16x3_kernel(const __nv_bfloat16* __restrict__ gAh,
                        const __nv_bfloat16* __restrict__ gAl,
                        const __nv_bfloat16* __restrict__ gBh,
                        const __nv_bfloat16* __restrict__ gBl,
                        __nv_bfloat16* __restrict__ oH,
                        __nv_bfloat16* __restrict__ oL,
                        float* __restrict__ oF,
                        const __nv_bfloat16* __restrict__ dH,
                        const __nv_bfloat16* __restrict__ dL,
                        float alpha, float beta, int alphaIdx, int sumsq)
{
    extern __shared__ char smem_raw[];
    const uint32_t smem_u = (smem_to_u32(smem_raw) + 1023u) & ~1023u;

    const int tid  = threadIdx.x;
    const int wid  = tid >> 5;
    const int lane = tid & 31;
    const int wm   = wid >> 1;        // 0..1 (64-row half)
    const int wn   = wid & 1;         // 0..1 (64-col half)
    const int row0 = blockIdx.y * 128;
    const int col0 = blockIdx.x * 128;

    // --- ldsm cores ---
    // non-TRA (row-major tiles, stride LDS_B)
    const uint32_t aCore = (uint32_t)(wm * 64 * LDS_B + (lane & 15) * LDS_B
                                      + (lane >> 4) * 16);
    const uint32_t bCore = (uint32_t)(wn * 64 * LDS_B + (lane & 7) * LDS_B
                                      + ((lane >> 3) & 1) * 16
                                      + ((lane >> 4) & 1) * 8 * LDS_B);
    // TRA (k-major tiles, stride TSTR). Quad order matches non-TRA regs:
    //  A: q0=(m0-7,k0-7) q1=(m8-15,k0-7) q2=(m0-7,k8-15) q3=(m8-15,k8-15)
    //  B: q0=(n0-7,k0-7) q1=(n0-7,k8-15) q2=(n8-15,k0-7) q3=(n8-15,k8-15)
    const uint32_t aCoreT = (uint32_t)(((lane & 7) + ((lane >> 4) & 1) * 8) * TSTR
                                       + ((lane >> 3) & 1) * 16 + wm * 128);
    const uint32_t bCoreT = (uint32_t)(((lane & 7) + ((lane >> 3) & 1) * 8) * TSTR
                                       + ((lane >> 4) & 1) * 16 + wn * 128);

    float acc[4][8][4];
    #pragma unroll
    for (int mt = 0; mt < 4; mt++)
        #pragma unroll
        for (int nt = 0; nt < 8; nt++)
            #pragma unroll
            for (int i = 0; i < 4; i++) acc[mt][nt][i] = 0.0f;

    const __nv_bfloat16* srcs[4] = {gAh, gAl, gBh, gBl};
    const int            rb[4]   = {row0, row0, col0, col0};

    const uint32_t stageB = TRA ? STAGE_T : STAGE_B;
    const uint32_t tileB  = TRA ? TILE_T  : TILE_B;

    auto issue_chunk = [&](int ch, int buf) {
        const int k0 = ch * CHUNK;
        const uint32_t sb = smem_u + buf * stageB;
        if (TRA) {
            // tile: 32 k-rows x 128 cols (256B data + 16B pad)
            #pragma unroll
            for (int t = 0; t < 4; t++)
                #pragma unroll
                for (int i = 0; i < 4; i++) {
                    int id = tid + i * 128;       // 0..511 = 32 rows x 16
                    int r = id >> 4, c16 = id & 15;
                    cp16(sb + t * TILE_T + (uint32_t)(r * TSTR + c16 * 16),
                         srcs[t] + (size_t)(k0 + r) * GK + rb[t] + c16 * 8);
                }
        } else {
            #pragma unroll
            for (int t = 0; t < 4; t++)
                #pragma unroll
                for (int i = 0; i < 4; i++) {
                    int id = tid + i * 128;       // 0..511 = 128 rows x 4
                    int r = id >> 2, c16 = id & 3;
                    cp16(sb + t * TILE_B + (uint32_t)(r * LDS_B + c16 * 16),
                         srcs[t] + (size_t)(rb[t] + r) * GK + k0 + c16 * 8);
                }
        }
        CP_COMMIT();
    };

    issue_chunk(0, 0);
    for (int ch = 0; ch < NCH; ch++) {
        const int buf = ch & 1;
        if (ch + 1 < NCH) { issue_chunk(ch + 1, buf ^ 1); CP_WAIT1(); }
        else              { CP_WAIT0(); }
        __syncthreads();

        const uint32_t sb = smem_u + buf * stageB;
        #pragma unroll
        for (int ks = 0; ks < 2; ks++) {
            const uint32_t kofB = TRA ? (uint32_t)(ks * 16 * TSTR) : (uint32_t)(ks * 32);
            uint32_t bh[8][2], bl[8][2];
            #pragma unroll
            for (int p = 0; p < 4; p++) {
                uint32_t t4[4];
                if (TRA) ldsm_x4_t(t4, sb + 2 * tileB + bCoreT + kofB + p * 32);
                else     ldsm_x4  (t4, sb + 2 * tileB + bCore  + kofB + p * 16 * LDS_B);
                bh[2 * p][0] = t4[0]; bh[2 * p][1] = t4[1];
                bh[2 * p + 1][0] = t4[2]; bh[2 * p + 1][1] = t4[3];
            }
            #pragma unroll
            for (int p = 0; p < 4; p++) {
                uint32_t t4[4];
                if (TRA) ldsm_x4_t(t4, sb + 3 * tileB + bCoreT + kofB + p * 32);
                else     ldsm_x4  (t4, sb + 3 * tileB + bCore  + kofB + p * 16 * LDS_B);
                bl[2 * p][0] = t4[0]; bl[2 * p][1] = t4[1];
                bl[2 * p + 1][0] = t4[2]; bl[2 * p + 1][1] = t4[3];
            }
            #pragma unroll
            for (int mt = 0; mt < 4; mt++) {
                uint32_t ah[4], al[4];
                if (TRA) {
                    ldsm_x4_t(ah, sb + aCoreT + kofB + mt * 32);
                    ldsm_x4_t(al, sb + tileB + aCoreT + kofB + mt * 32);
                } else {
                    ldsm_x4(ah, sb + aCore + kofB + mt * 16 * LDS_B);
                    ldsm_x4(al, sb + tileB + aCore + kofB + mt * 16 * LDS_B);
                }
                #pragma unroll
                for (int nt = 0; nt < 8; nt++) mma_bf16(acc[mt][nt], ah, bh[nt]);
                #pragma unroll
                for (int nt = 0; nt < 8; nt++) mma_bf16(acc[mt][nt], ah, bl[nt]);
                #pragma unroll
                for (int nt = 0; nt < 8; nt++) mma_bf16(acc[mt][nt], al, bh[nt]);
            }
        }
        __syncthreads();
    }

    // -------- epilogue: optional write, then optional sumsq --------
    float aEff = alpha;
    if (alphaIdx >= 0) aEff *= g_scalars[alphaIdx];
    const int gid = lane >> 2, tig = lane & 3;
    const int rowBase = row0 + wm * 64;
    const int colBase = col0 + wn * 64;

    if (oF || oH) {
        #pragma unroll
        for (int mt = 0; mt < 4; mt++)
            #pragma unroll
            for (int nt = 0; nt < 8; nt++)
                #pragma unroll
                for (int h = 0; h < 2; h++) {
                    const int r  = rowBase + mt * 16 + gid + h * 8;
                    const int cc = colBase + nt * 8 + tig * 2;
                    const size_t ro = (size_t)r * GK + cc;
                    float v0 = aEff * acc[mt][nt][2 * h];
                    float v1 = aEff * acc[mt][nt][2 * h + 1];
                    if (dH) {
                        __nv_bfloat162 h2 = *reinterpret_cast<const __nv_bfloat162*>(dH + ro);
                        __nv_bfloat162 l2 = *reinterpret_cast<const __nv_bfloat162*>(dL + ro);
                        v0 += beta * (__bfloat162float(h2.x) + __bfloat162float(l2.x));
                        v1 += beta * (__bfloat162float(h2.y) + __bfloat162float(l2.y));
                    }
                    if (oF)
                        *reinterpret_cast<float2*>(oF + ro) = make_float2(v0, v1);
                    if (oH) {
                        __nv_bfloat16 h0 = __float2bfloat16(v0);
                        __nv_bfloat16 h1 = __float2bfloat16(v1);
                        __nv_bfloat16 l0 = __float2bfloat16(v0 - __bfloat162float(h0));
                        __nv_bfloat16 l1 = __float2bfloat16(v1 - __bfloat162float(h1));
                        *reinterpret_cast<__nv_bfloat162*>(oH + ro) = __halves2bfloat162(h0, h1);
                        *reinterpret_cast<__nv_bfloat162*>(oL + ro) = __halves2bfloat162(l0, l1);
                    }
                }
    }
    if (sumsq) {
        double s = 0.0;
        #pragma unroll
        for (int mt = 0; mt < 4; mt++)
            #pragma unroll
            for (int nt = 0; nt < 8; nt++)
                #pragma unroll
                for (int i = 0; i < 4; i++) {
                    float v = acc[mt][nt][i];
                    s += (double)v * (double)v;
                }
        #pragma unroll
        for (int o = 16; o > 0; o >>= 1) s += __shfl_down_sync(0xffffffffu, s, o);
        double* sred = reinterpret_cast<double*>(smem_raw);
        __syncthreads();
        if (lane == 0) sred[wid] = s;
        __syncthreads();
        if (wid == 0) {
            s = (lane < 4) ? sred[lane] : 0.0;
            #pragma unroll
            for (int o = 2; o > 0; o >>= 1) s += __shfl_down_sync(0xffffffffu, s, o);
            if (lane == 0) atomicAdd(&g_accum, s);
        }
    }
}

// ============================================================================
// Elementwise kernels
// ============================================================================
__global__ void zero_accum_kernel() { g_accum = 0.0; }

__global__ void finalize_kernel(const float* __restrict__ gamma)
{
    double fro2   = g_accum;                   // ||M^2||_F^2 (spectrum = wwt's)
    double w_norm = pow(fro2, 0.125) + 1e-8;
    g_scalars[0] = (float)w_norm;
    g_scalars[1] = (float)(1.0 / w_norm);
    g_scalars[2] = (float)w_norm * gamma[0];
    double s2 = 1.0 / (w_norm * w_norm);
    g_scalars[3] = (float)s2;
    g_scalars[4] = (float)(s2 * s2);
}

__global__ void split_kernel(const float* __restrict__ src,
                             __nv_bfloat16* __restrict__ dHo,
                             __nv_bfloat16* __restrict__ dLo, int scaleIdx)
{
    float s = (scaleIdx >= 0) ? g_scalars[scaleIdx] : 1.0f;
    size_t i = ((size_t)blockIdx.x * 256 + threadIdx.x) * 4;
    float4 v = *reinterpret_cast<const float4*>(src + i);
    float f[4] = {v.x * s, v.y * s, v.z * s, v.w * s};
    __nv_bfloat16 h[4], l[4];
    #pragma unroll
    for (int j = 0; j < 4; j++) {
        h[j] = __float2bfloat16(f[j]);
        l[j] = __float2bfloat16(f[j] - __bfloat162float(h[j]));
    }
    *reinterpret_cast<__nv_bfloat162*>(dHo + i)     = __halves2bfloat162(h[0], h[1]);
    *reinterpret_cast<__nv_bfloat162*>(dHo + i + 2) = __halves2bfloat162(h[2], h[3]);
    *reinterpret_cast<__nv_bfloat162*>(dLo + i)     = __halves2bfloat162(l[0], l[1]);
    *reinterpret_cast<__nv_bfloat162*>(dLo + i + 2) = __halves2bfloat162(l[2], l[3]);
}

// T0 = (c/w_norm^4)*M2 + (b/w_norm^2)*M ; M2 in (Eh,El), M in (Mh,Ml);
// result overwrites (Eh,El) as a hi/lo pair.
__global__ void t0_combine_kernel(const __nv_bfloat16* __restrict__ Mh,
                                  const __nv_bfloat16* __restrict__ Ml,
                                  __nv_bfloat16* __restrict__ Eh,
                                  __nv_bfloat16* __restrict__ El,
                                  float b, float c)
{
    const float cb = c * g_scalars[4];
    const float bb = b * g_scalars[3];
    size_t i = ((size_t)blockIdx.x * 256 + threadIdx.x) * 2;
    __nv_bfloat162 m2h = *reinterpret_cast<const __nv_bfloat162*>(Eh + i);
    __nv_bfloat162 m2l = *reinterpret_cast<const __nv_bfloat162*>(El + i);
    __nv_bfloat162 mh  = *reinterpret_cast<const __nv_bfloat162*>(Mh + i);
    __nv_bfloat162 ml  = *reinterpret_cast<const __nv_bfloat162*>(Ml + i);
    float v0 = cb * (__bfloat162float(m2h.x) + __bfloat162float(m2l.x))
             + bb * (__bfloat162float(mh.x)  + __bfloat162float(ml.x));
    float v1 = cb * (__bfloat162float(m2h.y) + __bfloat162float(m2l.y))
             + bb * (__bfloat162float(mh.y)  + __bfloat162float(ml.y));
    __nv_bfloat16 h0 = __float2bfloat16(v0);
    __nv_bfloat16 h1 = __float2bfloat16(v1);
    __nv_bfloat16 l0 = __float2bfloat16(v0 - __bfloat162float(h0));
    __nv_bfloat16 l1 = __float2bfloat16(v1 - __bfloat162float(h1));
    *reinterpret_cast<__nv_bfloat162*>(Eh + i) = __halves2bfloat162(h0, h1);
    *reinterpret_cast<__nv_bfloat162*>(El + i) = __halves2bfloat162(l0, l1);
}

// ============================================================================
// Host orchestration (graph-capturable: kernel launches only)
// ============================================================================
static const float PE_COEF[8][3] = {
    {7.2086f, -15.5131f, 9.0178f}, {3.9623f, -2.5813f, 0.4542f},
    {3.9466f, -2.5765f, 0.4544f}, {3.8991f, -2.5671f, 0.4566f},
    {3.7186f, -2.5308f, 0.4653f}, {3.1390f, -2.3073f, 0.4733f},
    {2.1715f, -1.5246f, 0.3885f}, {1.8648f, -1.2224f, 0.3577f},
};

struct BPtr { __nv_bfloat16 *h, *l; };

static inline void run_gemm(int Mrows, BPtr A, BPtr B,
                            BPtr out, float* oF, BPtr D,
                            float alpha, float beta, int alphaIdx, int sumsq)
{
    cudaFuncSetAttribute(gemm_bf16x3_kernel<0>,
                         cudaFuncAttributeMaxDynamicSharedMemorySize, SMEM_NEED);
    dim3 grid(GK / 128, Mrows / 128), block(128);
    gemm_bf16x3_kernel<0><<<grid, block, SMEM_NEED>>>(
        A.h, A.l, B.h, B.l, out.h, out.l, oF, D.h, D.l,
        alpha, beta, alphaIdx, sumsq);
}

// C = S^T S from row-major S (TRA mode)
static inline void run_gemm_tt(BPtr S, BPtr out, int sumsq)
{
    cudaFuncSetAttribute(gemm_bf16x3_kernel<1>,
                         cudaFuncAttributeMaxDynamicSharedMemorySize, SMEM_NEED);
    dim3 grid(GK / 128, GK / 128), block(128);
    gemm_bf16x3_kernel<1><<<grid, block, SMEM_NEED>>>(
        S.h, S.l, S.h, S.l, out.h, out.l, nullptr, nullptr, nullptr,
        1.0f, 0.0f, -1, sumsq);
}

extern "C" void kernel_launch(void* const* d_in, const int* in_sizes, int n_in,
                              void* d_out, int out_size)
{
    const float* x      = (const float*)d_in[0];
    const float* weight = (const float*)d_in[1];
    const float* gamma  = (const float*)d_in[2];
    float*       out    = (float*)d_out;
    const int M_out = in_sizes[0] / GK;      // 8192

    auto sym = [](const void* s) {
        void* p; cudaGetSymbolAddress(&p, s); return (__nv_bfloat16*)p;
    };
    BPtr w  = {sym(g_wh),  sym(g_wl)};
    BPtr u0 = {sym(g_u0h), sym(g_u0l)};
    BPtr u1 = {sym(g_u1h), sym(g_u1l)};
    BPtr g  = {sym(g_gh),  sym(g_gl)};
    BPtr e  = {sym(g_eh),  sym(g_el)};
    BPtr X  = {sym(g_xh),  sym(g_xl)};
    BPtr nil = {nullptr, nullptr};

    // ---- M = W^T W (TRA, no transpose); w_norm = ||M^2||_F^0.25 + eps ----
    zero_accum_kernel<<<1, 1>>>();
    split_kernel<<<MAT / 4 / 256, 256>>>(weight, w.h, w.l, -1);
    run_gemm_tt(w, g, 0);                                              // M -> g
    run_gemm(GK, g, g, e, nullptr, nil, 1.0f, 0.0f, -1, 1);            // M^2 -> e, + sumsq
    finalize_kernel<<<1, 1>>>(gamma);

    // ---- U0 = W / w_norm ; X split ----
    split_kernel<<<MAT / 4 / 256, 256>>>(weight, u0.h, u0.l, 1);
    split_kernel<<<XMAT / 4 / 256, 256>>>(x, X.h, X.l, -1);

    // ---- 8 Polar Express iterations (it 0: g,T elementwise from M,M^2) ----
    BPtr U = u0, Un = u1;
    for (int it = 0; it < 8; it++) {
        float a = PE_COEF[it][0], bb = PE_COEF[it][1], c = PE_COEF[it][2];
        if (it == 0) {
            t0_combine_kernel<<<MAT / 2 / 256, 256>>>(g.h, g.l, e.h, e.l, bb, c);
        } else {
            run_gemm_tt(U, g, 0);                                      // g = U^T U
            run_gemm(GK, g, g, e, nullptr, g, c, bb, -1, 0);           // T = c g^2 + b g
        }
        run_gemm(GK, U, e, Un, nullptr, U, 1.0f, a, -1, 0);            // Un = U T + a U
        BPtr tp = U; U = Un; Un = tp;
    }

    // ---- out = (w_norm * gamma) * X @ U^T ----
    run_gemm(M_out, X, U, nil, out, nil, 1.0f, 0.0f, 2, 0);
}